// round 13
// baseline (speedup 1.0000x reference)
#include <cuda_runtime.h>
#include <stdint.h>

#define N_NODES 100000
#define N_EDGES 1600000
#define LOG2E 1.4426950408889634f

// ---------------- device scratch (no allocations allowed) ----------------
__device__ int    g_is64;
__device__ int    g_deg[N_NODES];
__device__ int    g_rowptr[N_NODES + 1];
__device__ int    g_pos[N_NODES];
__device__ int    g_srcs[N_EDGES];
__device__ float4 g_h2[N_NODES];
__device__ float  g_a2s[N_NODES];
__device__ float  g_a2d[N_NODES];
__device__ float  g_ps[8], g_qs[8], g_pd[8], g_qd[8];

__device__ __forceinline__ float ex2f(float x) {
    float r;
    asm("ex2.approx.ftz.f32 %0, %1;" : "=f"(r) : "f"(x));
    return r;
}

// Decode edge value at logical index i from raw 32-bit view, honoring dtype flag.
__device__ __forceinline__ int edge_val(const int* __restrict__ ei, int i) {
    return g_is64 ? ei[2 * i] : ei[i];
}

// ---------------- dtype detection ----------------
// If data is int64 (values < 2^31), every odd 32-bit word of the first 1024
// elements is 0. If int32, odd words are random node ids -> some nonzero.
__global__ void k_detect(const int* __restrict__ ei) {
    int t = threadIdx.x;
    int nz = 0;
    for (int k = t; k < 1024; k += 32) nz |= ei[2 * k + 1];
#pragma unroll
    for (int off = 16; off > 0; off >>= 1) nz |= __shfl_xor_sync(0xffffffffu, nz, off);
    if (t == 0) g_is64 = (nz == 0) ? 1 : 0;
}

// ---------------- CSR build ----------------
__global__ void k_zero() {
    int i = blockIdx.x * blockDim.x + threadIdx.x;
    if (i < N_NODES) g_deg[i] = 0;
}

__global__ void k_hist(const int* __restrict__ ei) {
    int i = blockIdx.x * blockDim.x + threadIdx.x;
    if (i < N_EDGES) {
        int d = edge_val(ei, N_EDGES + i);
        if ((unsigned)d < (unsigned)N_NODES) atomicAdd(&g_deg[d], 1);
    }
}

__global__ void k_scan() {
    __shared__ int sh[1024];
    const int IPT = (N_NODES + 1023) / 1024;  // 98
    int t = threadIdx.x;
    int base = t * IPT;
    int local = 0;
    for (int k = 0; k < IPT; k++) {
        int i = base + k;
        if (i < N_NODES) local += g_deg[i];
    }
    sh[t] = local;
    __syncthreads();
    for (int off = 1; off < 1024; off <<= 1) {
        int v = (t >= off) ? sh[t - off] : 0;
        __syncthreads();
        sh[t] += v;
        __syncthreads();
    }
    int run = (t == 0) ? 0 : sh[t - 1];
    for (int k = 0; k < IPT; k++) {
        int i = base + k;
        if (i < N_NODES) {
            g_rowptr[i] = run;
            g_pos[i] = run;
            run += g_deg[i];
        }
    }
    if (t == 1023) g_rowptr[N_NODES] = sh[1023];
}

__global__ void k_scatter(const int* __restrict__ ei) {
    int i = blockIdx.x * blockDim.x + threadIdx.x;
    if (i < N_EDGES) {
        int s = edge_val(ei, i);
        int d = edge_val(ei, N_EDGES + i);
        if ((unsigned)d < (unsigned)N_NODES && (unsigned)s < (unsigned)N_NODES) {
            int p = atomicAdd(&g_pos[d], 1);
            if ((unsigned)p < (unsigned)N_EDGES) g_srcs[p] = s;
        }
    }
}

// ---------------- precompute rank-2 attention projections ----------------
// a_src[n,h] = x0*ps[h] + x1*qs[h] ; a_dst[n,h] = x0*pd[h] + x1*qd[h]
// all pre-scaled by log2(e) so the edge kernel uses ex2 directly.
__global__ void k_pre(const float* __restrict__ W1,
                      const float* __restrict__ as1,
                      const float* __restrict__ ad1) {
    int h = threadIdx.x;
    if (h < 8) {
        float ps = 0.f, qs = 0.f, pd = 0.f, qd = 0.f;
        for (int c = 0; c < 16; c++) {
            int idx = h * 16 + c;
            float w0 = W1[idx], w1 = W1[128 + idx];
            float a = as1[idx], d = ad1[idx];
            ps += w0 * a;
            qs += w1 * a;
            pd += w0 * d;
            qd += w1 * d;
        }
        g_ps[h] = ps * LOG2E;
        g_qs[h] = qs * LOG2E;
        g_pd[h] = pd * LOG2E;
        g_qd[h] = qd * LOG2E;
    }
}

// ---------------- layer 1: edge softmax-aggregate + node transform + W2 fold ----------------
// warp per dst node; lane = 8*edge_stripe + head (4 stripes x 8 heads)
__global__ void __launch_bounds__(256) k_layer1(
    const float* __restrict__ x,
    const float* __restrict__ W1,
    const float* __restrict__ b1,
    const float* __restrict__ W2,
    const float* __restrict__ as2,
    const float* __restrict__ ad2) {
    int warp = (blockIdx.x * blockDim.x + threadIdx.x) >> 5;
    if (warp >= N_NODES) return;
    int lane = threadIdx.x & 31;
    int h = lane & 7;
    int es = lane >> 3;

    const float2* x2 = (const float2*)x;
    float2 xn = __ldg(&x2[warp]);
    float P = g_ps[h], Q = g_qs[h];
    float A = fmaf(xn.x, g_pd[h], xn.y * g_qd[h]);  // log2e * a_dst[n,h]

    int beg = g_rowptr[warp];
    int end = g_rowptr[warp + 1];

    float S0 = 0.f, S1 = 0.f, SS = 0.f;
    for (int i = beg + es; i < end; i += 4) {
        int s = g_srcs[i];
        float2 xs = __ldg(&x2[s]);
        float t = fmaf(xs.y, Q, fmaf(xs.x, P, A));  // log2e*(a_src+a_dst)
        t = fmaxf(t, 0.2f * t);                     // leaky relu (scale-invariant)
        float ex = ex2f(t);                         // exp(lrelu(e))
        S0 = fmaf(ex, xs.x, S0);
        S1 = fmaf(ex, xs.y, S1);
        SS += ex;
    }
    // reduce over the 4 edge stripes (lanes differing by 8, 16)
    S0 += __shfl_xor_sync(0xffffffffu, S0, 8);
    S0 += __shfl_xor_sync(0xffffffffu, S0, 16);
    S1 += __shfl_xor_sync(0xffffffffu, S1, 8);
    S1 += __shfl_xor_sync(0xffffffffu, S1, 16);
    SS += __shfl_xor_sync(0xffffffffu, SS, 8);
    SS += __shfl_xor_sync(0xffffffffu, SS, 16);

    // redistribute: lane l now produces channels 4l..4l+3, head = l>>2
    int hl = lane >> 2;
    float s0 = __shfl_sync(0xffffffffu, S0, hl);
    float s1 = __shfl_sync(0xffffffffu, S1, hl);
    float ss = __shfl_sync(0xffffffffu, SS, hl);
    float inv = 1.0f / (ss + 1e-16f);

    // out1[c] = (S0*W1[0,c] + S1*W1[1,c])/sum + b1[c], relu; fold into W2
    float hp0 = 0.f, hp1 = 0.f, hp2 = 0.f, hp3 = 0.f;
#pragma unroll
    for (int k = 0; k < 4; k++) {
        int c = 4 * lane + k;
        float o = fmaf(s0, __ldg(&W1[c]), s1 * __ldg(&W1[128 + c])) * inv + __ldg(&b1[c]);
        o = fmaxf(o, 0.0f);  // relu
        float w0 = __ldg(&W2[c * 4 + 0]);
        float w1 = __ldg(&W2[c * 4 + 1]);
        float w2 = __ldg(&W2[c * 4 + 2]);
        float w3 = __ldg(&W2[c * 4 + 3]);
        hp0 = fmaf(o, w0, hp0);
        hp1 = fmaf(o, w1, hp1);
        hp2 = fmaf(o, w2, hp2);
        hp3 = fmaf(o, w3, hp3);
    }
#pragma unroll
    for (int off = 16; off > 0; off >>= 1) {
        hp0 += __shfl_xor_sync(0xffffffffu, hp0, off);
        hp1 += __shfl_xor_sync(0xffffffffu, hp1, off);
        hp2 += __shfl_xor_sync(0xffffffffu, hp2, off);
        hp3 += __shfl_xor_sync(0xffffffffu, hp3, off);
    }
    if (lane == 0) {
        g_h2[warp] = make_float4(hp0, hp1, hp2, hp3);
        float a0 = __ldg(&as2[0]), a1 = __ldg(&as2[1]), a2 = __ldg(&as2[2]), a3 = __ldg(&as2[3]);
        float d0 = __ldg(&ad2[0]), d1 = __ldg(&ad2[1]), d2 = __ldg(&ad2[2]), d3 = __ldg(&ad2[3]);
        g_a2s[warp] = (hp0 * a0 + hp1 * a1 + hp2 * a2 + hp3 * a3) * LOG2E;
        g_a2d[warp] = (hp0 * d0 + hp1 * d1 + hp2 * d2 + hp3 * d3) * LOG2E;
    }
}

// ---------------- layer 2: edge softmax-aggregate + bias + log_softmax ----------------
__global__ void __launch_bounds__(256) k_layer2(const float* __restrict__ b2,
                                                float* __restrict__ out) {
    int warp = (blockIdx.x * blockDim.x + threadIdx.x) >> 5;
    if (warp >= N_NODES) return;
    int lane = threadIdx.x & 31;

    float a2dn = g_a2d[warp];
    int beg = g_rowptr[warp];
    int end = g_rowptr[warp + 1];

    float a0 = 0.f, a1 = 0.f, a2 = 0.f, a3 = 0.f, ss = 0.f;
    for (int i = beg + lane; i < end; i += 32) {
        int s = g_srcs[i];
        float t = g_a2s[s] + a2dn;
        t = fmaxf(t, 0.2f * t);
        float ex = ex2f(t);
        float4 hv = g_h2[s];
        a0 = fmaf(ex, hv.x, a0);
        a1 = fmaf(ex, hv.y, a1);
        a2 = fmaf(ex, hv.z, a2);
        a3 = fmaf(ex, hv.w, a3);
        ss += ex;
    }
#pragma unroll
    for (int off = 16; off > 0; off >>= 1) {
        a0 += __shfl_xor_sync(0xffffffffu, a0, off);
        a1 += __shfl_xor_sync(0xffffffffu, a1, off);
        a2 += __shfl_xor_sync(0xffffffffu, a2, off);
        a3 += __shfl_xor_sync(0xffffffffu, a3, off);
        ss += __shfl_xor_sync(0xffffffffu, ss, off);
    }
    if (lane == 0) {
        float inv = 1.0f / (ss + 1e-16f);
        float o0 = a0 * inv + __ldg(&b2[0]);
        float o1 = a1 * inv + __ldg(&b2[1]);
        float o2 = a2 * inv + __ldg(&b2[2]);
        float o3 = a3 * inv + __ldg(&b2[3]);
        float m = fmaxf(fmaxf(o0, o1), fmaxf(o2, o3));
        float se = expf(o0 - m) + expf(o1 - m) + expf(o2 - m) + expf(o3 - m);
        float ls = m + logf(se);
        out[warp * 4 + 0] = o0 - ls;
        out[warp * 4 + 1] = o1 - ls;
        out[warp * 4 + 2] = o2 - ls;
        out[warp * 4 + 3] = o3 - ls;
    }
}

// ---------------- launch ----------------
extern "C" void kernel_launch(void* const* d_in, const int* in_sizes, int n_in,
                              void* d_out, int out_size) {
    const float* x   = (const float*)d_in[0];
    const int*   ei  = (const int*)d_in[1];  // raw 32-bit view; dtype detected at runtime
    const float* W1  = (const float*)d_in[2];
    const float* as1 = (const float*)d_in[3];
    const float* ad1 = (const float*)d_in[4];
    const float* b1  = (const float*)d_in[5];
    const float* W2  = (const float*)d_in[6];
    const float* as2 = (const float*)d_in[7];
    const float* ad2 = (const float*)d_in[8];
    const float* b2  = (const float*)d_in[9];
    float*       out = (float*)d_out;

    k_detect<<<1, 32>>>(ei);
    k_zero<<<(N_NODES + 255) / 256, 256>>>();
    k_pre<<<1, 32>>>(W1, as1, ad1);
    k_hist<<<(N_EDGES + 255) / 256, 256>>>(ei);
    k_scan<<<1, 1024>>>();
    k_scatter<<<(N_EDGES + 255) / 256, 256>>>(ei);
    k_layer1<<<(N_NODES * 32 + 255) / 256, 256>>>(x, W1, b1, W2, as2, ad2);
    k_layer2<<<(N_NODES * 32 + 255) / 256, 256>>>(b2, out);
}

// round 14
// speedup vs baseline: 1.8024x; 1.8024x over previous
#include <cuda_runtime.h>
#include <stdint.h>

#define N_NODES 100000
#define N_EDGES 1600000
#define LOG2E 1.4426950408889634f
#define SCAN_B 1024
#define SCAN_NB ((N_NODES + SCAN_B - 1) / SCAN_B)  // 98

// ---------------- device scratch (no allocations allowed) ----------------
__device__ int    g_is64;
__device__ int    g_deg[N_NODES];
__device__ int    g_incl[N_NODES];
__device__ int    g_bsum[SCAN_NB];
__device__ int    g_rowptr[N_NODES + 1];
__device__ int    g_pos[N_NODES];
__device__ int    g_srcs[N_EDGES];
__device__ float4 g_h2[N_NODES];
__device__ float  g_a2s[N_NODES];
__device__ float  g_a2d[N_NODES];
__device__ float  g_ps[8], g_qs[8], g_pd[8], g_qd[8];

__device__ __forceinline__ float ex2f(float x) {
    float r;
    asm("ex2.approx.ftz.f32 %0, %1;" : "=f"(r) : "f"(x));
    return r;
}

// ---------------- fused init: zero deg + dtype detect + rank-2 precompute ----------------
__global__ void k_init(const int* __restrict__ ei,
                       const float* __restrict__ W1,
                       const float* __restrict__ as1,
                       const float* __restrict__ ad1) {
    int i = blockIdx.x * blockDim.x + threadIdx.x;
    if (i < N_NODES) g_deg[i] = 0;
    if (blockIdx.x == 0) {
        int t = threadIdx.x;
        if (t < 32) {
            // int64 edge data (values < 2^31) => odd 32-bit words all zero
            int nz = 0;
            for (int k = t; k < 1024; k += 32) nz |= ei[2 * k + 1];
#pragma unroll
            for (int off = 16; off > 0; off >>= 1)
                nz |= __shfl_xor_sync(0xffffffffu, nz, off);
            if (t == 0) g_is64 = (nz == 0) ? 1 : 0;
        } else if (t < 40) {
            int h = t - 32;
            float ps = 0.f, qs = 0.f, pd = 0.f, qd = 0.f;
            for (int c = 0; c < 16; c++) {
                int idx = h * 16 + c;
                float w0 = W1[idx], w1 = W1[128 + idx];
                float a = as1[idx], d = ad1[idx];
                ps += w0 * a;
                qs += w1 * a;
                pd += w0 * d;
                qd += w1 * d;
            }
            g_ps[h] = ps * LOG2E;
            g_qs[h] = qs * LOG2E;
            g_pd[h] = pd * LOG2E;
            g_qd[h] = qd * LOG2E;
        }
    }
}

// ---------------- CSR build ----------------
__global__ void k_hist(const int* __restrict__ ei) {
    int i = blockIdx.x * blockDim.x + threadIdx.x;
    if (i < N_EDGES) {
        int d = g_is64 ? ei[2 * (N_EDGES + i)] : ei[N_EDGES + i];
        if ((unsigned)d < (unsigned)N_NODES) atomicAdd(&g_deg[d], 1);
    }
}

// coalesced per-block inclusive scan + block partial
__global__ void k_scanA() {
    __shared__ int sh[SCAN_B];
    int t = threadIdx.x;
    int i = blockIdx.x * SCAN_B + t;
    int v = (i < N_NODES) ? g_deg[i] : 0;
    sh[t] = v;
    __syncthreads();
#pragma unroll
    for (int off = 1; off < SCAN_B; off <<= 1) {
        int u = (t >= off) ? sh[t - off] : 0;
        __syncthreads();
        sh[t] += u;
        __syncthreads();
    }
    if (i < N_NODES) g_incl[i] = sh[t];
    if (t == SCAN_B - 1) g_bsum[blockIdx.x] = sh[t];
}

// each block redundantly scans the 98 partials, then writes rowptr/pos
__global__ void k_scanB() {
    __shared__ int sb[128];
    int t = threadIdx.x;
    if (t < 128) sb[t] = (t < SCAN_NB) ? g_bsum[t] : 0;
    __syncthreads();
#pragma unroll
    for (int off = 1; off < 128; off <<= 1) {
        int u = 0;
        if (t < 128 && t >= off) u = sb[t - off];
        __syncthreads();
        if (t < 128) sb[t] += u;
        __syncthreads();
    }
    int offset = (blockIdx.x == 0) ? 0 : sb[blockIdx.x - 1];
    int i = blockIdx.x * SCAN_B + t;
    if (i < N_NODES) {
        int incl = g_incl[i];
        int exc = offset + incl - g_deg[i];
        g_rowptr[i] = exc;
        g_pos[i] = exc;
        if (i == N_NODES - 1) g_rowptr[N_NODES] = offset + incl;
    }
}

__global__ void k_scatter(const int* __restrict__ ei) {
    int i = blockIdx.x * blockDim.x + threadIdx.x;
    if (i < N_EDGES) {
        int s, d;
        if (g_is64) {
            s = ei[2 * i];
            d = ei[2 * (N_EDGES + i)];
        } else {
            s = ei[i];
            d = ei[N_EDGES + i];
        }
        if ((unsigned)d < (unsigned)N_NODES && (unsigned)s < (unsigned)N_NODES) {
            int p = atomicAdd(&g_pos[d], 1);
            if ((unsigned)p < (unsigned)N_EDGES) g_srcs[p] = s;
        }
    }
}

// ---------------- layer 1: edge softmax-aggregate + node transform + W2 fold ----------------
// warp per dst node; lane = 8*edge_stripe + head (4 stripes x 8 heads)
__global__ void __launch_bounds__(256) k_layer1(
    const float* __restrict__ x,
    const float* __restrict__ W1,
    const float* __restrict__ b1,
    const float* __restrict__ W2,
    const float* __restrict__ as2,
    const float* __restrict__ ad2) {
    int warp = (blockIdx.x * blockDim.x + threadIdx.x) >> 5;
    if (warp >= N_NODES) return;
    int lane = threadIdx.x & 31;
    int h = lane & 7;
    int es = lane >> 3;

    const float2* x2 = (const float2*)x;
    float2 xn = __ldg(&x2[warp]);
    float P = g_ps[h], Q = g_qs[h];
    float A = fmaf(xn.x, g_pd[h], xn.y * g_qd[h]);  // log2e * a_dst[n,h]

    int beg = g_rowptr[warp];
    int end = g_rowptr[warp + 1];

    float S0 = 0.f, S1 = 0.f, SS = 0.f;
    int i = beg + es;
    int s_next = (i < end) ? g_srcs[i] : 0;
    while (i < end) {
        int s = s_next;
        i += 4;
        if (i < end) s_next = g_srcs[i];           // prefetch next index
        float2 xs = __ldg(&x2[s]);
        float t = fmaf(xs.y, Q, fmaf(xs.x, P, A)); // log2e*(a_src+a_dst)
        t = fmaxf(t, 0.2f * t);                    // leaky relu (scale-invariant)
        float ex = ex2f(t);                        // exp(lrelu(e))
        S0 = fmaf(ex, xs.x, S0);
        S1 = fmaf(ex, xs.y, S1);
        SS += ex;
    }
    // reduce over the 4 edge stripes (lanes differing by 8, 16)
    S0 += __shfl_xor_sync(0xffffffffu, S0, 8);
    S0 += __shfl_xor_sync(0xffffffffu, S0, 16);
    S1 += __shfl_xor_sync(0xffffffffu, S1, 8);
    S1 += __shfl_xor_sync(0xffffffffu, S1, 16);
    SS += __shfl_xor_sync(0xffffffffu, SS, 8);
    SS += __shfl_xor_sync(0xffffffffu, SS, 16);

    // redistribute: lane l now produces channels 4l..4l+3, head = l>>2
    int hl = lane >> 2;
    float s0 = __shfl_sync(0xffffffffu, S0, hl);
    float s1 = __shfl_sync(0xffffffffu, S1, hl);
    float ss = __shfl_sync(0xffffffffu, SS, hl);
    float inv = 1.0f / (ss + 1e-16f);

    // out1[c] = (S0*W1[0,c] + S1*W1[1,c])/sum + b1[c], relu; fold into W2
    float hp0 = 0.f, hp1 = 0.f, hp2 = 0.f, hp3 = 0.f;
#pragma unroll
    for (int k = 0; k < 4; k++) {
        int c = 4 * lane + k;
        float o = fmaf(s0, __ldg(&W1[c]), s1 * __ldg(&W1[128 + c])) * inv + __ldg(&b1[c]);
        o = fmaxf(o, 0.0f);  // relu
        hp0 = fmaf(o, __ldg(&W2[c * 4 + 0]), hp0);
        hp1 = fmaf(o, __ldg(&W2[c * 4 + 1]), hp1);
        hp2 = fmaf(o, __ldg(&W2[c * 4 + 2]), hp2);
        hp3 = fmaf(o, __ldg(&W2[c * 4 + 3]), hp3);
    }
#pragma unroll
    for (int off = 16; off > 0; off >>= 1) {
        hp0 += __shfl_xor_sync(0xffffffffu, hp0, off);
        hp1 += __shfl_xor_sync(0xffffffffu, hp1, off);
        hp2 += __shfl_xor_sync(0xffffffffu, hp2, off);
        hp3 += __shfl_xor_sync(0xffffffffu, hp3, off);
    }
    if (lane == 0) {
        g_h2[warp] = make_float4(hp0, hp1, hp2, hp3);
        float a0 = __ldg(&as2[0]), a1 = __ldg(&as2[1]), a2 = __ldg(&as2[2]), a3 = __ldg(&as2[3]);
        float d0 = __ldg(&ad2[0]), d1 = __ldg(&ad2[1]), d2 = __ldg(&ad2[2]), d3 = __ldg(&ad2[3]);
        g_a2s[warp] = (hp0 * a0 + hp1 * a1 + hp2 * a2 + hp3 * a3) * LOG2E;
        g_a2d[warp] = (hp0 * d0 + hp1 * d1 + hp2 * d2 + hp3 * d3) * LOG2E;
    }
}

// ---------------- layer 2: edge softmax-aggregate + bias + log_softmax ----------------
__global__ void __launch_bounds__(256) k_layer2(const float* __restrict__ b2,
                                                float* __restrict__ out) {
    int warp = (blockIdx.x * blockDim.x + threadIdx.x) >> 5;
    if (warp >= N_NODES) return;
    int lane = threadIdx.x & 31;

    float a2dn = g_a2d[warp];
    int beg = g_rowptr[warp];
    int end = g_rowptr[warp + 1];

    float a0 = 0.f, a1 = 0.f, a2 = 0.f, a3 = 0.f, ss = 0.f;
    int i = beg + lane;
    int s_next = (i < end) ? g_srcs[i] : 0;
    while (i < end) {
        int s = s_next;
        i += 32;
        if (i < end) s_next = g_srcs[i];
        float t = g_a2s[s] + a2dn;
        t = fmaxf(t, 0.2f * t);
        float ex = ex2f(t);
        float4 hv = g_h2[s];
        a0 = fmaf(ex, hv.x, a0);
        a1 = fmaf(ex, hv.y, a1);
        a2 = fmaf(ex, hv.z, a2);
        a3 = fmaf(ex, hv.w, a3);
        ss += ex;
    }
#pragma unroll
    for (int off = 16; off > 0; off >>= 1) {
        a0 += __shfl_xor_sync(0xffffffffu, a0, off);
        a1 += __shfl_xor_sync(0xffffffffu, a1, off);
        a2 += __shfl_xor_sync(0xffffffffu, a2, off);
        a3 += __shfl_xor_sync(0xffffffffu, a3, off);
        ss += __shfl_xor_sync(0xffffffffu, ss, off);
    }
    if (lane == 0) {
        float inv = 1.0f / (ss + 1e-16f);
        float o0 = a0 * inv + __ldg(&b2[0]);
        float o1 = a1 * inv + __ldg(&b2[1]);
        float o2 = a2 * inv + __ldg(&b2[2]);
        float o3 = a3 * inv + __ldg(&b2[3]);
        float m = fmaxf(fmaxf(o0, o1), fmaxf(o2, o3));
        float se = expf(o0 - m) + expf(o1 - m) + expf(o2 - m) + expf(o3 - m);
        float ls = m + logf(se);
        out[warp * 4 + 0] = o0 - ls;
        out[warp * 4 + 1] = o1 - ls;
        out[warp * 4 + 2] = o2 - ls;
        out[warp * 4 + 3] = o3 - ls;
    }
}

// ---------------- launch ----------------
extern "C" void kernel_launch(void* const* d_in, const int* in_sizes, int n_in,
                              void* d_out, int out_size) {
    const float* x   = (const float*)d_in[0];
    const int*   ei  = (const int*)d_in[1];  // raw 32-bit view; dtype detected at runtime
    const float* W1  = (const float*)d_in[2];
    const float* as1 = (const float*)d_in[3];
    const float* ad1 = (const float*)d_in[4];
    const float* b1  = (const float*)d_in[5];
    const float* W2  = (const float*)d_in[6];
    const float* as2 = (const float*)d_in[7];
    const float* ad2 = (const float*)d_in[8];
    const float* b2  = (const float*)d_in[9];
    float*       out = (float*)d_out;

    k_init<<<(N_NODES + 255) / 256, 256>>>(ei, W1, as1, ad1);
    k_hist<<<(N_EDGES + 255) / 256, 256>>>(ei);
    k_scanA<<<SCAN_NB, SCAN_B>>>();
    k_scanB<<<SCAN_NB, SCAN_B>>>();
    k_scatter<<<(N_EDGES + 255) / 256, 256>>>(ei);
    k_layer1<<<(N_NODES * 32 + 255) / 256, 256>>>(x, W1, b1, W2, as2, ad2);
    k_layer2<<<(N_NODES * 32 + 255) / 256, 256>>>(b2, out);
}